// round 15
// baseline (speedup 1.0000x reference)
#include <cuda_runtime.h>

// Problem constants
#define Bn     16
#define Rn     128
#define Tn     128
#define Hn     32
#define En     64
#define VOCABn 258
#define NTOK   (Bn*Rn*Tn)   // 262144

// Scratch
__device__ float g_out_h[(size_t)NTOK * Hn];
__device__ int   g_progress[Rn * 8];     // one flag per (row, 2-batch warp)
__device__ float g_G[VOCABn * 96];       // W_ih0[:, :64] @ embed_table[v]^T

typedef unsigned long long ull;

// ---------------------------------------------------------------------------

__device__ __forceinline__ int ld_poll(const int* p) {
    int v;
    asm volatile("ld.global.cg.b32 %0, [%1];" : "=r"(v) : "l"(p));
    return v;
}
__device__ __forceinline__ void st_rel(int* p, int v) {
    asm volatile("st.global.release.gpu.b32 [%0], %1;" :: "l"(p), "r"(v) : "memory");
}
__device__ __forceinline__ float sigm(float x) {
    return __fdividef(1.0f, 1.0f + __expf(-x));
}
__device__ __forceinline__ float tanh_f(float x) {
    float e = __expf(2.0f * x);
    return 1.0f - __fdividef(2.0f, e + 1.0f);
}
__device__ __forceinline__ ull fma2(ull a, ull b, ull c) {
    ull d;
    asm("fma.rn.f32x2 %0, %1, %2, %3;" : "=l"(d) : "l"(a), "l"(b), "l"(c));
    return d;
}
__device__ __forceinline__ float hsum(ull a) {
    float lo, hi;
    asm("mov.b64 {%0, %1}, %2;" : "=f"(lo), "=f"(hi) : "l"(a));
    return lo + hi;
}

// ---------------------------------------------------------------------------
// 2-batch i-paired triple-plane dot, smem weights.
template<int G, int SW, int SI>
__device__ __forceinline__ void dotacc2(
    const float* __restrict__ pR, const float* __restrict__ pZ, const float* __restrict__ pN,
    const float* __restrict__ in, int j,
    ull aR[2], ull aZ[2], ull aN[2])
{
    const float* wR = pR + j * SW;
    const float* wZ = pZ + j * SW;
    const float* wN = pN + j * SW;
#pragma unroll
    for (int g = 0; g < G; ++g) {
        const int i0 = g * 4;
        ulonglong2 w0 = *(const ulonglong2*)(wR + i0);
        ulonglong2 w1 = *(const ulonglong2*)(wZ + i0);
        ulonglong2 w2 = *(const ulonglong2*)(wN + i0);
        ulonglong2 v0 = *(const ulonglong2*)(in + 0 * SI + i0);
        ulonglong2 v1 = *(const ulonglong2*)(in + 1 * SI + i0);
        aR[0] = fma2(w0.x, v0.x, aR[0]); aZ[0] = fma2(w1.x, v0.x, aZ[0]); aN[0] = fma2(w2.x, v0.x, aN[0]);
        aR[1] = fma2(w0.x, v1.x, aR[1]); aZ[1] = fma2(w1.x, v1.x, aZ[1]); aN[1] = fma2(w2.x, v1.x, aN[1]);
        aR[0] = fma2(w0.y, v0.y, aR[0]); aZ[0] = fma2(w1.y, v0.y, aZ[0]); aN[0] = fma2(w2.y, v0.y, aN[0]);
        aR[1] = fma2(w0.y, v1.y, aR[1]); aZ[1] = fma2(w1.y, v1.y, aZ[1]); aN[1] = fma2(w2.y, v1.y, aN[1]);
    }
}

// 2-batch dot with REGISTER weights (lane-private rows, no LDS for weights).
__device__ __forceinline__ void dotacc2r(
    const ull* wR, const ull* wZ, const ull* wN,
    const float* __restrict__ in,
    ull aR[2], ull aZ[2], ull aN[2])
{
#pragma unroll
    for (int g = 0; g < 8; ++g) {
        const int i0 = g * 4;
        ull w0x = wR[2*g], w0y = wR[2*g+1];
        ull w1x = wZ[2*g], w1y = wZ[2*g+1];
        ull w2x = wN[2*g], w2y = wN[2*g+1];
        ulonglong2 v0 = *(const ulonglong2*)(in + 0 * 32 + i0);
        ulonglong2 v1 = *(const ulonglong2*)(in + 1 * 32 + i0);
        aR[0] = fma2(w0x, v0.x, aR[0]); aZ[0] = fma2(w1x, v0.x, aZ[0]); aN[0] = fma2(w2x, v0.x, aN[0]);
        aR[1] = fma2(w0x, v1.x, aR[1]); aZ[1] = fma2(w1x, v1.x, aZ[1]); aN[1] = fma2(w2x, v1.x, aN[1]);
        aR[0] = fma2(w0y, v0.y, aR[0]); aZ[0] = fma2(w1y, v0.y, aZ[0]); aN[0] = fma2(w2y, v0.y, aN[0]);
        aR[1] = fma2(w0y, v1.y, aR[1]); aZ[1] = fma2(w1y, v1.y, aZ[1]); aN[1] = fma2(w2y, v1.y, aN[1]);
    }
}

// ---------------------------------------------------------------------------
// prep: G[v][g] = sum_e wih0[g][e] * embed_table[v][e]
__global__ void prep_kernel(const float* __restrict__ wih0,
                            const float* __restrict__ emb)
{
    const int v = blockIdx.x;
    const int g = threadIdx.x;    // 96 threads
    const float* wr = wih0 + g * 65;
    const float* er = emb + v * En;
    float acc = 0.0f;
#pragma unroll 8
    for (int e = 0; e < En; ++e) acc += wr[e] * er[e];
    g_G[v * 96 + g] = acc;
}

// ---------------------------------------------------------------------------
// Smem layout (floats). Planes: R, Z, N per matrix, row stride 36.
#define PL_SM    1152                  // 32*36
#define P_HH0    0
#define P_IH1    (1*3456)
#define P_HH1    (2*3456)
#define P_IH2    (3*3456)
#define P_HH2    (4*3456)
#define P_M      (5*3456)              // folded W_ih0 @ W_h2e^T
#define P_STG    (6*3456)              // 20736
#define STG_WARP 256                   // h0/h1/h2/pv: 2*32 each
#define P_BF     (P_STG + 8*STG_WARP)  // folded layer-0 gate bias [96]
#define SM_FLOATS (P_BF + 128)
#define SMEM_BYTES (SM_FLOATS * 4)     // ~91.6 KB

extern __shared__ float s_rnn[];

__global__ __launch_bounds__(256, 1) void rnn_kernel(
    const int*   __restrict__ x,
    const float* __restrict__ wih0, const float* __restrict__ whh0,
    const float* __restrict__ bih0, const float* __restrict__ bhh0,
    const float* __restrict__ wih1, const float* __restrict__ whh1,
    const float* __restrict__ bih1, const float* __restrict__ bhh1,
    const float* __restrict__ wih2, const float* __restrict__ whh2,
    const float* __restrict__ bih2, const float* __restrict__ bhh2,
    const float* __restrict__ wh2e, const float* __restrict__ bh2e)
{
    const int r   = blockIdx.x;
    const int tid = threadIdx.x;
    const float rf = (float)r * (2.0f / 128.0f) - 1.0f;

    for (int n = tid; n < SM_FLOATS; n += 256) s_rnn[n] = 0.0f;
    __syncthreads();

    // stage recurrent weights into gate planes
    {
        const float* srcs[5] = { whh0, wih1, whh1, wih2, whh2 };
        const int    offs[5] = { P_HH0, P_IH1, P_HH1, P_IH2, P_HH2 };
#pragma unroll
        for (int m = 0; m < 5; ++m) {
            const float* src = srcs[m];
            float* dst = s_rnn + offs[m];
            for (int n = tid; n < 96 * 32; n += 256) {
                int gI = n >> 5, i = n & 31;
                dst[(gI >> 5) * PL_SM + (gI & 31) * 36 + i] = src[n];
            }
        }
    }
    // fold M[g][h] = sum_e wih0[g][e] * wh2e[e][h]
    for (int n = tid; n < 96 * 32; n += 256) {
        int gI = n >> 5, h = n & 31;
        const float* wr = wih0 + gI * 65;
        float acc = wr[64] * __ldg(&wh2e[64 * 32 + h]);
#pragma unroll 4
        for (int e = 0; e < 64; ++e) acc += wr[e] * __ldg(&wh2e[e * 32 + h]);
        s_rnn[P_M + (gI >> 5) * PL_SM + (gI & 31) * 36 + h] = acc;
    }
    // fold bf[g] = bih0[g] + sum_e wih0[g][e]*bh2e[e] + wih0[g][64]*rf
    if (tid < 96) {
        const float* wr = wih0 + tid * 65;
        float acc = bih0[tid] + wr[64] * rf;
#pragma unroll 5
        for (int e = 0; e < 65; ++e) acc += wr[e] * __ldg(&bh2e[e]);
        s_rnn[P_BF + tid] = acc;
    }
    __syncthreads();

    const int g = tid >> 5;   // warp id 0..7, handles batches 2g, 2g+1
    const int j = tid & 31;
    const int b0 = 2 * g;

    const float* hh0R = s_rnn + P_HH0, *hh0Z = hh0R + PL_SM, *hh0N = hh0Z + PL_SM;
    const float* ih1R = s_rnn + P_IH1, *ih1Z = ih1R + PL_SM, *ih1N = ih1Z + PL_SM;
    const float* hh1R = s_rnn + P_HH1, *hh1Z = hh1R + PL_SM, *hh1N = hh1Z + PL_SM;
    const float* ih2R = s_rnn + P_IH2, *ih2Z = ih2R + PL_SM, *ih2N = ih2Z + PL_SM;
    const float* hh2R = s_rnn + P_HH2, *hh2Z = hh2R + PL_SM, *hh2N = hh2Z + PL_SM;
    const float* MR   = s_rnn + P_M,   *MZ   = MR + PL_SM,   *MN   = MZ + PL_SM;

    // ---- register-cache hh1 + hh2 rows for this lane (96 ull) ----
    ull c1R[16], c1Z[16], c1N[16], c2R[16], c2Z[16], c2N[16];
#pragma unroll
    for (int k = 0; k < 16; ++k) {
        c1R[k] = *(const ull*)(hh1R + j * 36 + 2 * k);
        c1Z[k] = *(const ull*)(hh1Z + j * 36 + 2 * k);
        c1N[k] = *(const ull*)(hh1N + j * 36 + 2 * k);
        c2R[k] = *(const ull*)(hh2R + j * 36 + 2 * k);
        c2Z[k] = *(const ull*)(hh2Z + j * 36 + 2 * k);
        c2N[k] = *(const ull*)(hh2N + j * 36 + 2 * k);
    }

    float* stg   = s_rnn + P_STG + g * STG_WARP;
    float* st_h0 = stg;            // [b*32 + j], b in {0,1}
    float* st_h1 = stg + 64;
    float* st_h2 = stg + 128;
    float* st_pv = stg + 192;

    const float brc0 = s_rnn[P_BF + j]      + bhh0[j];
    const float bzc0 = s_rnn[P_BF + 32 + j] + bhh0[32 + j];
    const float bin0 = s_rnn[P_BF + 64 + j];
    const float bhn0 = bhh0[64 + j];
    const float brc1 = bih1[j] + bhh1[j], bzc1 = bih1[32+j] + bhh1[32+j];
    const float bin1 = bih1[64+j],        bhn1 = bhh1[64+j];
    const float brc2 = bih2[j] + bhh2[j], bzc2 = bih2[32+j] + bhh2[32+j];
    const float bin2 = bih2[64+j],        bhn2 = bhh2[64+j];

    int* myflag = &g_progress[r * 8 + g];
    const int* waitflag = (r > 0) ? &g_progress[(r - 1) * 8 + g] : (const int*)0;
    int seen = 0;

    float h0[2] = {0,0}, h1[2] = {0,0}, h2[2] = {0,0};

    // ---- prologue: G values for t=0, x for t=1 ----
    float gc[6];
    int xvn[2];
    {
        int xv[2];
#pragma unroll
        for (int b = 0; b < 2; ++b) xv[b] = __ldg(&x[((b0 + b) * Rn + r) * Tn]);
#pragma unroll
        for (int b = 0; b < 2; ++b) {
            gc[b*3+0] = __ldg(&g_G[xv[b] * 96 + j]);
            gc[b*3+1] = __ldg(&g_G[xv[b] * 96 + 32 + j]);
            gc[b*3+2] = __ldg(&g_G[xv[b] * 96 + 64 + j]);
        }
        const int t1 = (Tn > 1) ? 1 : 0;
#pragma unroll
        for (int b = 0; b < 2; ++b) xvn[b] = __ldg(&x[((b0 + b) * Rn + r) * Tn + t1]);
    }

    for (int t = 0; t < Tn; ++t) {
        // ---- prefetch x[t+2], G[x[t+1]] ----
        const int tnx = (t + 2 < Tn) ? t + 2 : Tn - 1;
        int xv2[2];
#pragma unroll
        for (int b = 0; b < 2; ++b) xv2[b] = __ldg(&x[((b0 + b) * Rn + r) * Tn + tnx]);
        float gnx[6];
#pragma unroll
        for (int b = 0; b < 2; ++b) {
            gnx[b*3+0] = __ldg(&g_G[xvn[b] * 96 + j]);
            gnx[b*3+1] = __ldg(&g_G[xvn[b] * 96 + 32 + j]);
            gnx[b*3+2] = __ldg(&g_G[xvn[b] * 96 + 64 + j]);
        }

        // ---- layer-0 recurrent dot (pre-wait) ----
        ull ar0[2] = {0,0}, az0[2] = {0,0}, anh0[2] = {0,0};
        dotacc2<8, 36, 32>(hh0R, hh0Z, hh0N, st_h0, j, ar0, az0, anh0);

        // ---- WAIT + previous-row coupling ----
        ull ani0[2] = {0,0};
        if (r > 0) {
            if (seen <= t) {
                seen = ld_poll(waitflag);
                while (seen <= t) { __nanosleep(20); seen = ld_poll(waitflag); }
                asm volatile("" ::: "memory");
            }
            __syncwarp();
#pragma unroll
            for (int b = 0; b < 2; ++b)
                st_pv[b * 32 + j] = __ldcg(&g_out_h[(size_t)(((b0 + b) * Rn + (r - 1)) * Tn + t) * Hn + j]);
            __syncwarp();
            dotacc2<8, 36, 32>(MR, MZ, MN, st_pv, j, ar0, az0, ani0);
        }

        // ---- layer-0 activations ----
#pragma unroll
        for (int b = 0; b < 2; ++b) {
            float gr = sigm(hsum(ar0[b]) + gc[b*3+0] + brc0);
            float gz = sigm(hsum(az0[b]) + gc[b*3+1] + bzc0);
            float gnv = tanh_f(hsum(ani0[b]) + gc[b*3+2] + bin0 + gr * (hsum(anh0[b]) + bhn0));
            h0[b] = gnv + gz * (h0[b] - gnv);
        }
        __syncwarp();
#pragma unroll
        for (int b = 0; b < 2; ++b) st_h0[b * 32 + j] = h0[b];
        __syncwarp();

        // ---- layer 1: ih1 (smem) + hh1 (registers) ----
        {
            ull ar1[2] = {0,0}, az1[2] = {0,0}, anh1[2] = {0,0}, ani[2] = {0,0};
            dotacc2r(c1R, c1Z, c1N, st_h1, ar1, az1, anh1);
            dotacc2<8, 36, 32>(ih1R, ih1Z, ih1N, st_h0, j, ar1, az1, ani);
#pragma unroll
            for (int b = 0; b < 2; ++b) {
                float gr = sigm(hsum(ar1[b]) + brc1);
                float gz = sigm(hsum(az1[b]) + bzc1);
                float gnv = tanh_f(hsum(ani[b]) + bin1 + gr * (hsum(anh1[b]) + bhn1));
                h1[b] = gnv + gz * (h1[b] - gnv);
            }
            __syncwarp();
#pragma unroll
            for (int b = 0; b < 2; ++b) st_h1[b * 32 + j] = h1[b];
            __syncwarp();
        }

        // ---- layer 2: ih2 (smem) + hh2 (registers) ----
        {
            ull ar2[2] = {0,0}, az2[2] = {0,0}, anh2[2] = {0,0}, ani[2] = {0,0};
            dotacc2r(c2R, c2Z, c2N, st_h2, ar2, az2, anh2);
            dotacc2<8, 36, 32>(ih2R, ih2Z, ih2N, st_h1, j, ar2, az2, ani);
#pragma unroll
            for (int b = 0; b < 2; ++b) {
                float gr = sigm(hsum(ar2[b]) + brc2);
                float gz = sigm(hsum(az2[b]) + bzc2);
                float gnv = tanh_f(hsum(ani[b]) + bin2 + gr * (hsum(anh2[b]) + bhn2));
                h2[b] = gnv + gz * (h2[b] - gnv);
            }
            __syncwarp();
#pragma unroll
            for (int b = 0; b < 2; ++b) st_h2[b * 32 + j] = h2[b];
            __syncwarp();
        }

        // ---- publish + release ----
#pragma unroll
        for (int b = 0; b < 2; ++b)
            __stcg(&g_out_h[(size_t)(((b0 + b) * Rn + r) * Tn + t) * Hn + j], h2[b]);
        st_rel(myflag, t + 1);

        // rotate prefetch
#pragma unroll
        for (int k = 0; k < 6; ++k) gc[k] = gnx[k];
#pragma unroll
        for (int b = 0; b < 2; ++b) xvn[b] = xv2[b];
    }
}

// ---------------------------------------------------------------------------
// Output projection: weights in registers, pre-duplicated h pairs in dynamic smem.
#define PT 128
#define PROJ_DYN_BYTES (PT * 72 * 4)

extern __shared__ float h_s[];   // [PT][72]: h duplicated {h,h}, stride 72 floats

__global__ __launch_bounds__(256) void proj_kernel(
    const float* __restrict__ w_out,
    const float* __restrict__ b_out,
    float* __restrict__ pred)
{
    __shared__ float w_s[32 * 260];     // [h][v] padded
    __shared__ float b_s[260];

    const int tid = threadIdx.x;

    if (blockIdx.x == 0) {
        for (int n = tid; n < Rn * 8; n += 256) g_progress[n] = 0;   // reset for next replay
    }

    for (int n = tid; n < VOCABn * 32; n += 256) {
        int v = n >> 5, h = n & 31;
        w_s[h * 260 + v] = w_out[n];
    }
    for (int n = tid; n < VOCABn; n += 256) b_s[n] = b_out[n];

    const size_t tok0 = (size_t)blockIdx.x * PT;
    const float* src = g_out_h + tok0 * 32;
    for (int n = tid; n < PT * 32; n += 256) {
        int i = n >> 5, h = n & 31;
        float v = src[n];
        h_s[i * 72 + 2 * h]     = v;
        h_s[i * 72 + 2 * h + 1] = v;
    }
    __syncthreads();

    const int warp = tid >> 5, lane = tid & 31;
    const int p = ((warp & 3) << 5) + lane;        // 0..127
    const int tokbase = (warp >> 2) * 64;

    ull wreg[32];
#pragma unroll
    for (int h = 0; h < 32; ++h)
        wreg[h] = *(const ull*)&w_s[h * 260 + 2 * p];
    const ull b2 = *(const ull*)&b_s[2 * p];

#pragma unroll 1
    for (int tg = 0; tg < 16; ++tg) {
        const int tk = tokbase + tg * 4;
        ull a0 = b2, a1 = b2, a2 = b2, a3 = b2;
        const float* h0p = &h_s[(tk + 0) * 72];
        const float* h1p = &h_s[(tk + 1) * 72];
        const float* h2p = &h_s[(tk + 2) * 72];
        const float* h3p = &h_s[(tk + 3) * 72];
#pragma unroll
        for (int hq = 0; hq < 8; ++hq) {
            ulonglong2 qa0 = *(const ulonglong2*)(h0p + hq * 8);
            ulonglong2 qb0 = *(const ulonglong2*)(h0p + hq * 8 + 4);
            ulonglong2 qa1 = *(const ulonglong2*)(h1p + hq * 8);
            ulonglong2 qb1 = *(const ulonglong2*)(h1p + hq * 8 + 4);
            ulonglong2 qa2 = *(const ulonglong2*)(h2p + hq * 8);
            ulonglong2 qb2 = *(const ulonglong2*)(h2p + hq * 8 + 4);
            ulonglong2 qa3 = *(const ulonglong2*)(h3p + hq * 8);
            ulonglong2 qb3 = *(const ulonglong2*)(h3p + hq * 8 + 4);
            a0 = fma2(wreg[hq*4+0], qa0.x, a0);
            a1 = fma2(wreg[hq*4+0], qa1.x, a1);
            a2 = fma2(wreg[hq*4+0], qa2.x, a2);
            a3 = fma2(wreg[hq*4+0], qa3.x, a3);
            a0 = fma2(wreg[hq*4+1], qa0.y, a0);
            a1 = fma2(wreg[hq*4+1], qa1.y, a1);
            a2 = fma2(wreg[hq*4+1], qa2.y, a2);
            a3 = fma2(wreg[hq*4+1], qa3.y, a3);
            a0 = fma2(wreg[hq*4+2], qb0.x, a0);
            a1 = fma2(wreg[hq*4+2], qb1.x, a1);
            a2 = fma2(wreg[hq*4+2], qb2.x, a2);
            a3 = fma2(wreg[hq*4+2], qb3.x, a3);
            a0 = fma2(wreg[hq*4+3], qb0.y, a0);
            a1 = fma2(wreg[hq*4+3], qb1.y, a1);
            a2 = fma2(wreg[hq*4+3], qb2.y, a2);
            a3 = fma2(wreg[hq*4+3], qb3.y, a3);
        }
        float* outp = &pred[(tok0 + tk) * VOCABn + 2 * p];
        *(ull*)(outp + 0 * VOCABn) = a0;
        *(ull*)(outp + 1 * VOCABn) = a1;
        *(ull*)(outp + 2 * VOCABn) = a2;
        *(ull*)(outp + 3 * VOCABn) = a3;
    }

    // tail pair 128 (v = 256, 257)
    if (tid < PT) {
        ull acc = *(const ull*)&b_s[256];
        const float* hp = &h_s[tid * 72];
#pragma unroll
        for (int h = 0; h < 32; ++h)
            acc = fma2(*(const ull*)&w_s[h * 260 + 256],
                       *(const ull*)(hp + 2 * h), acc);
        *(ull*)&pred[(tok0 + tid) * VOCABn + 256] = acc;
    }
}

// ---------------------------------------------------------------------------

extern "C" void kernel_launch(void* const* d_in, const int* in_sizes, int n_in,
                              void* d_out, int out_size)
{
    const int*   x     = (const int*)  d_in[0];
    const float* emb   = (const float*)d_in[1];
    const float* wih0  = (const float*)d_in[2];
    const float* whh0  = (const float*)d_in[3];
    const float* bih0  = (const float*)d_in[4];
    const float* bhh0  = (const float*)d_in[5];
    const float* wih1  = (const float*)d_in[6];
    const float* whh1  = (const float*)d_in[7];
    const float* bih1  = (const float*)d_in[8];
    const float* bhh1  = (const float*)d_in[9];
    const float* wih2  = (const float*)d_in[10];
    const float* whh2  = (const float*)d_in[11];
    const float* bih2  = (const float*)d_in[12];
    const float* bhh2  = (const float*)d_in[13];
    const float* wh2e  = (const float*)d_in[14];
    const float* bh2e  = (const float*)d_in[15];
    const float* w_out = (const float*)d_in[16];
    const float* b_out = (const float*)d_in[17];
    float* pred = (float*)d_out;

    cudaFuncSetAttribute(rnn_kernel, cudaFuncAttributeMaxDynamicSharedMemorySize, SMEM_BYTES);
    cudaFuncSetAttribute(proj_kernel, cudaFuncAttributeMaxDynamicSharedMemorySize, PROJ_DYN_BYTES);

    prep_kernel<<<VOCABn, 96>>>(wih0, emb);
    rnn_kernel<<<Rn, 256, SMEM_BYTES>>>(x,
        wih0, whh0, bih0, bhh0,
        wih1, whh1, bih1, bhh1,
        wih2, whh2, bih2, bhh2,
        wh2e, bh2e);
    proj_kernel<<<NTOK / PT, 256, PROJ_DYN_BYTES>>>(w_out, b_out, pred);
}

// round 16
// speedup vs baseline: 1.6815x; 1.6815x over previous
#include <cuda_runtime.h>

// Problem constants
#define Bn     16
#define Rn     128
#define Tn     128
#define Hn     32
#define En     64
#define VOCABn 258
#define NTOK   (Bn*Rn*Tn)   // 262144

// Scratch
__device__ float g_out_h[(size_t)NTOK * Hn];
__device__ int   g_progress[Rn * 8];     // one flag per (row, 2-batch warp)
__device__ float g_G[VOCABn * 96];       // W_ih0[:, :64] @ embed_table[v]^T

typedef unsigned long long ull;

// ---------------------------------------------------------------------------

__device__ __forceinline__ int ld_poll(const int* p) {
    int v;
    asm volatile("ld.global.cg.b32 %0, [%1];" : "=r"(v) : "l"(p));
    return v;
}
__device__ __forceinline__ void st_rel(int* p, int v) {
    asm volatile("st.global.release.gpu.b32 [%0], %1;" :: "l"(p), "r"(v) : "memory");
}
__device__ __forceinline__ float sigm(float x) {
    return __fdividef(1.0f, 1.0f + __expf(-x));
}
__device__ __forceinline__ float tanh_f(float x) {
    float e = __expf(2.0f * x);
    return 1.0f - __fdividef(2.0f, e + 1.0f);
}
__device__ __forceinline__ ull fma2(ull a, ull b, ull c) {
    ull d;
    asm("fma.rn.f32x2 %0, %1, %2, %3;" : "=l"(d) : "l"(a), "l"(b), "l"(c));
    return d;
}
__device__ __forceinline__ float hsum(ull a) {
    float lo, hi;
    asm("mov.b64 {%0, %1}, %2;" : "=f"(lo), "=f"(hi) : "l"(a));
    return lo + hi;
}

// ---------------------------------------------------------------------------
// 2-batch i-paired triple-plane dot, smem weights.
template<int G, int SW, int SI>
__device__ __forceinline__ void dotacc2(
    const float* __restrict__ pR, const float* __restrict__ pZ, const float* __restrict__ pN,
    const float* __restrict__ in, int j,
    ull aR[2], ull aZ[2], ull aN[2])
{
    const float* wR = pR + j * SW;
    const float* wZ = pZ + j * SW;
    const float* wN = pN + j * SW;
#pragma unroll
    for (int g = 0; g < G; ++g) {
        const int i0 = g * 4;
        ulonglong2 w0 = *(const ulonglong2*)(wR + i0);
        ulonglong2 w1 = *(const ulonglong2*)(wZ + i0);
        ulonglong2 w2 = *(const ulonglong2*)(wN + i0);
        ulonglong2 v0 = *(const ulonglong2*)(in + 0 * SI + i0);
        ulonglong2 v1 = *(const ulonglong2*)(in + 1 * SI + i0);
        aR[0] = fma2(w0.x, v0.x, aR[0]); aZ[0] = fma2(w1.x, v0.x, aZ[0]); aN[0] = fma2(w2.x, v0.x, aN[0]);
        aR[1] = fma2(w0.x, v1.x, aR[1]); aZ[1] = fma2(w1.x, v1.x, aZ[1]); aN[1] = fma2(w2.x, v1.x, aN[1]);
        aR[0] = fma2(w0.y, v0.y, aR[0]); aZ[0] = fma2(w1.y, v0.y, aZ[0]); aN[0] = fma2(w2.y, v0.y, aN[0]);
        aR[1] = fma2(w0.y, v1.y, aR[1]); aZ[1] = fma2(w1.y, v1.y, aZ[1]); aN[1] = fma2(w2.y, v1.y, aN[1]);
    }
}

// 2-batch dot with REGISTER weights for one matrix (lane-private rows).
// Identical i-pair accumulation order to dotacc2.
__device__ __forceinline__ void dotacc2r(
    const ull* wR, const ull* wZ, const ull* wN,
    const float* __restrict__ in,
    ull aR[2], ull aZ[2], ull aN[2])
{
#pragma unroll
    for (int g = 0; g < 8; ++g) {
        const int i0 = g * 4;
        ull w0x = wR[2*g], w0y = wR[2*g+1];
        ull w1x = wZ[2*g], w1y = wZ[2*g+1];
        ull w2x = wN[2*g], w2y = wN[2*g+1];
        ulonglong2 v0 = *(const ulonglong2*)(in + 0 * 32 + i0);
        ulonglong2 v1 = *(const ulonglong2*)(in + 1 * 32 + i0);
        aR[0] = fma2(w0x, v0.x, aR[0]); aZ[0] = fma2(w1x, v0.x, aZ[0]); aN[0] = fma2(w2x, v0.x, aN[0]);
        aR[1] = fma2(w0x, v1.x, aR[1]); aZ[1] = fma2(w1x, v1.x, aZ[1]); aN[1] = fma2(w2x, v1.x, aN[1]);
        aR[0] = fma2(w0y, v0.y, aR[0]); aZ[0] = fma2(w1y, v0.y, aZ[0]); aN[0] = fma2(w2y, v0.y, aN[0]);
        aR[1] = fma2(w0y, v1.y, aR[1]); aZ[1] = fma2(w1y, v1.y, aZ[1]); aN[1] = fma2(w2y, v1.y, aN[1]);
    }
}

// ---------------------------------------------------------------------------
// prep: G[v][g] = sum_e wih0[g][e] * embed_table[v][e]
__global__ void prep_kernel(const float* __restrict__ wih0,
                            const float* __restrict__ emb)
{
    const int v = blockIdx.x;
    const int g = threadIdx.x;    // 96 threads
    const float* wr = wih0 + g * 65;
    const float* er = emb + v * En;
    float acc = 0.0f;
#pragma unroll 8
    for (int e = 0; e < En; ++e) acc += wr[e] * er[e];
    g_G[v * 96 + g] = acc;
}

// ---------------------------------------------------------------------------
// Smem layout (floats). Planes: R, Z, N per matrix, row stride 36.
#define PL_SM    1152                  // 32*36
#define P_HH0    0
#define P_IH1    (1*3456)
#define P_HH1    (2*3456)
#define P_IH2    (3*3456)
#define P_HH2    (4*3456)
#define P_M      (5*3456)              // folded W_ih0 @ W_h2e^T
#define P_STG    (6*3456)              // 20736
#define STG_WARP 256                   // h0/h1/h2/pv: 2*32 each
#define P_BF     (P_STG + 8*STG_WARP)  // folded layer-0 gate bias [96]
#define SM_FLOATS (P_BF + 128)
#define SMEM_BYTES (SM_FLOATS * 4)     // ~91.6 KB

extern __shared__ float s_rnn[];

__global__ __launch_bounds__(256, 1) void rnn_kernel(
    const int*   __restrict__ x,
    const float* __restrict__ wih0, const float* __restrict__ whh0,
    const float* __restrict__ bih0, const float* __restrict__ bhh0,
    const float* __restrict__ wih1, const float* __restrict__ whh1,
    const float* __restrict__ bih1, const float* __restrict__ bhh1,
    const float* __restrict__ wih2, const float* __restrict__ whh2,
    const float* __restrict__ bih2, const float* __restrict__ bhh2,
    const float* __restrict__ wh2e, const float* __restrict__ bh2e)
{
    const int r   = blockIdx.x;
    const int tid = threadIdx.x;
    const float rf = (float)r * (2.0f / 128.0f) - 1.0f;

    for (int n = tid; n < SM_FLOATS; n += 256) s_rnn[n] = 0.0f;
    __syncthreads();

    // stage recurrent weights into gate planes
    {
        const float* srcs[5] = { whh0, wih1, whh1, wih2, whh2 };
        const int    offs[5] = { P_HH0, P_IH1, P_HH1, P_IH2, P_HH2 };
#pragma unroll
        for (int m = 0; m < 5; ++m) {
            const float* src = srcs[m];
            float* dst = s_rnn + offs[m];
            for (int n = tid; n < 96 * 32; n += 256) {
                int gI = n >> 5, i = n & 31;
                dst[(gI >> 5) * PL_SM + (gI & 31) * 36 + i] = src[n];
            }
        }
    }
    // fold M[g][h] = sum_e wih0[g][e] * wh2e[e][h]
    for (int n = tid; n < 96 * 32; n += 256) {
        int gI = n >> 5, h = n & 31;
        const float* wr = wih0 + gI * 65;
        float acc = wr[64] * __ldg(&wh2e[64 * 32 + h]);
#pragma unroll 4
        for (int e = 0; e < 64; ++e) acc += wr[e] * __ldg(&wh2e[e * 32 + h]);
        s_rnn[P_M + (gI >> 5) * PL_SM + (gI & 31) * 36 + h] = acc;
    }
    // fold bf[g] = bih0[g] + sum_e wih0[g][e]*bh2e[e] + wih0[g][64]*rf
    if (tid < 96) {
        const float* wr = wih0 + tid * 65;
        float acc = bih0[tid] + wr[64] * rf;
#pragma unroll 5
        for (int e = 0; e < 65; ++e) acc += wr[e] * __ldg(&bh2e[e]);
        s_rnn[P_BF + tid] = acc;
    }
    __syncthreads();

    const int g = tid >> 5;   // warp id 0..7, handles batches 2g, 2g+1
    const int j = tid & 31;
    const int b0 = 2 * g;

    const float* hh0R = s_rnn + P_HH0, *hh0Z = hh0R + PL_SM, *hh0N = hh0Z + PL_SM;
    const float* ih1R = s_rnn + P_IH1, *ih1Z = ih1R + PL_SM, *ih1N = ih1Z + PL_SM;
    const float* hh1R = s_rnn + P_HH1, *hh1Z = hh1R + PL_SM, *hh1N = hh1Z + PL_SM;
    const float* ih2R = s_rnn + P_IH2, *ih2Z = ih2R + PL_SM, *ih2N = ih2Z + PL_SM;
    const float* hh2R = s_rnn + P_HH2, *hh2Z = hh2R + PL_SM, *hh2N = hh2Z + PL_SM;
    const float* MR   = s_rnn + P_M,   *MZ   = MR + PL_SM,   *MN   = MZ + PL_SM;

    // ---- register-cache ONLY hh2 rows for this lane (48 ull = 96 regs) ----
    ull c2R[16], c2Z[16], c2N[16];
#pragma unroll
    for (int k = 0; k < 16; ++k) {
        c2R[k] = *(const ull*)(hh2R + j * 36 + 2 * k);
        c2Z[k] = *(const ull*)(hh2Z + j * 36 + 2 * k);
        c2N[k] = *(const ull*)(hh2N + j * 36 + 2 * k);
    }

    float* stg   = s_rnn + P_STG + g * STG_WARP;
    float* st_h0 = stg;            // [b*32 + j], b in {0,1}
    float* st_h1 = stg + 64;
    float* st_h2 = stg + 128;
    float* st_pv = stg + 192;

    const float brc0 = s_rnn[P_BF + j]      + bhh0[j];
    const float bzc0 = s_rnn[P_BF + 32 + j] + bhh0[32 + j];
    const float bin0 = s_rnn[P_BF + 64 + j];
    const float bhn0 = bhh0[64 + j];
    const float brc1 = bih1[j] + bhh1[j], bzc1 = bih1[32+j] + bhh1[32+j];
    const float bin1 = bih1[64+j],        bhn1 = bhh1[64+j];
    const float brc2 = bih2[j] + bhh2[j], bzc2 = bih2[32+j] + bhh2[32+j];
    const float bin2 = bih2[64+j],        bhn2 = bhh2[64+j];

    int* myflag = &g_progress[r * 8 + g];
    const int* waitflag = (r > 0) ? &g_progress[(r - 1) * 8 + g] : (const int*)0;
    int seen = 0;

    float h0[2] = {0,0}, h1[2] = {0,0}, h2[2] = {0,0};

    // ---- prologue: G values for t=0, x for t=1 ----
    float gc[6];
    int xvn[2];
    {
        int xv[2];
#pragma unroll
        for (int b = 0; b < 2; ++b) xv[b] = __ldg(&x[((b0 + b) * Rn + r) * Tn]);
#pragma unroll
        for (int b = 0; b < 2; ++b) {
            gc[b*3+0] = __ldg(&g_G[xv[b] * 96 + j]);
            gc[b*3+1] = __ldg(&g_G[xv[b] * 96 + 32 + j]);
            gc[b*3+2] = __ldg(&g_G[xv[b] * 96 + 64 + j]);
        }
        const int t1 = (Tn > 1) ? 1 : 0;
#pragma unroll
        for (int b = 0; b < 2; ++b) xvn[b] = __ldg(&x[((b0 + b) * Rn + r) * Tn + t1]);
    }

    for (int t = 0; t < Tn; ++t) {
        // ---- PRE-WAIT: prefetch + all recurrent (h(t-1)) dots ----
        const int tnx = (t + 2 < Tn) ? t + 2 : Tn - 1;
        int xv2[2];
#pragma unroll
        for (int b = 0; b < 2; ++b) xv2[b] = __ldg(&x[((b0 + b) * Rn + r) * Tn + tnx]);
        float gnx[6];
#pragma unroll
        for (int b = 0; b < 2; ++b) {
            gnx[b*3+0] = __ldg(&g_G[xvn[b] * 96 + j]);
            gnx[b*3+1] = __ldg(&g_G[xvn[b] * 96 + 32 + j]);
            gnx[b*3+2] = __ldg(&g_G[xvn[b] * 96 + 64 + j]);
        }

        ull ar0[2] = {0,0}, az0[2] = {0,0}, anh0[2] = {0,0};
        ull ar1[2] = {0,0}, az1[2] = {0,0}, anh1[2] = {0,0};
        ull ar2[2] = {0,0}, az2[2] = {0,0}, anh2[2] = {0,0};
        dotacc2<8, 36, 32>(hh0R, hh0Z, hh0N, st_h0, j, ar0, az0, anh0);
        dotacc2<8, 36, 32>(hh1R, hh1Z, hh1N, st_h1, j, ar1, az1, anh1);
        dotacc2r(c2R, c2Z, c2N, st_h2, ar2, az2, anh2);

        // ---- WAIT + previous-row coupling ----
        ull ani0[2] = {0,0};
        if (r > 0) {
            if (seen <= t) {
                seen = ld_poll(waitflag);
                while (seen <= t) { __nanosleep(20); seen = ld_poll(waitflag); }
                asm volatile("" ::: "memory");
            }
            __syncwarp();
#pragma unroll
            for (int b = 0; b < 2; ++b)
                st_pv[b * 32 + j] = __ldcg(&g_out_h[(size_t)(((b0 + b) * Rn + (r - 1)) * Tn + t) * Hn + j]);
            __syncwarp();
            dotacc2<8, 36, 32>(MR, MZ, MN, st_pv, j, ar0, az0, ani0);
        }

        // ---- layer-0 activations ----
#pragma unroll
        for (int b = 0; b < 2; ++b) {
            float gr = sigm(hsum(ar0[b]) + gc[b*3+0] + brc0);
            float gz = sigm(hsum(az0[b]) + gc[b*3+1] + bzc0);
            float gnv = tanh_f(hsum(ani0[b]) + gc[b*3+2] + bin0 + gr * (hsum(anh0[b]) + bhn0));
            h0[b] = gnv + gz * (h0[b] - gnv);
        }
        __syncwarp();
#pragma unroll
        for (int b = 0; b < 2; ++b) st_h0[b * 32 + j] = h0[b];
        __syncwarp();

        // ---- layer 1 ----
        {
            ull ani[2] = {0,0};
            dotacc2<8, 36, 32>(ih1R, ih1Z, ih1N, st_h0, j, ar1, az1, ani);
#pragma unroll
            for (int b = 0; b < 2; ++b) {
                float gr = sigm(hsum(ar1[b]) + brc1);
                float gz = sigm(hsum(az1[b]) + bzc1);
                float gnv = tanh_f(hsum(ani[b]) + bin1 + gr * (hsum(anh1[b]) + bhn1));
                h1[b] = gnv + gz * (h1[b] - gnv);
            }
            __syncwarp();
#pragma unroll
            for (int b = 0; b < 2; ++b) st_h1[b * 32 + j] = h1[b];
            __syncwarp();
        }

        // ---- layer 2 ----
        {
            ull ani[2] = {0,0};
            dotacc2<8, 36, 32>(ih2R, ih2Z, ih2N, st_h1, j, ar2, az2, ani);
#pragma unroll
            for (int b = 0; b < 2; ++b) {
                float gr = sigm(hsum(ar2[b]) + brc2);
                float gz = sigm(hsum(az2[b]) + bzc2);
                float gnv = tanh_f(hsum(ani[b]) + bin2 + gr * (hsum(anh2[b]) + bhn2));
                h2[b] = gnv + gz * (h2[b] - gnv);
            }
            __syncwarp();
#pragma unroll
            for (int b = 0; b < 2; ++b) st_h2[b * 32 + j] = h2[b];
            __syncwarp();
        }

        // ---- publish + release ----
#pragma unroll
        for (int b = 0; b < 2; ++b)
            __stcg(&g_out_h[(size_t)(((b0 + b) * Rn + r) * Tn + t) * Hn + j], h2[b]);
        st_rel(myflag, t + 1);

        // rotate prefetch
#pragma unroll
        for (int k = 0; k < 6; ++k) gc[k] = gnx[k];
#pragma unroll
        for (int b = 0; b < 2; ++b) xvn[b] = xv2[b];
    }
}

// ---------------------------------------------------------------------------
// Output projection: weights in registers, pre-duplicated h pairs in dynamic smem.
#define PT 128
#define PROJ_DYN_BYTES (PT * 72 * 4)

extern __shared__ float h_s[];   // [PT][72]: h duplicated {h,h}, stride 72 floats

__global__ __launch_bounds__(256) void proj_kernel(
    const float* __restrict__ w_out,
    const float* __restrict__ b_out,
    float* __restrict__ pred)
{
    __shared__ float w_s[32 * 260];     // [h][v] padded
    __shared__ float b_s[260];

    const int tid = threadIdx.x;

    if (blockIdx.x == 0) {
        for (int n = tid; n < Rn * 8; n += 256) g_progress[n] = 0;   // reset for next replay
    }

    for (int n = tid; n < VOCABn * 32; n += 256) {
        int v = n >> 5, h = n & 31;
        w_s[h * 260 + v] = w_out[n];
    }
    for (int n = tid; n < VOCABn; n += 256) b_s[n] = b_out[n];

    const size_t tok0 = (size_t)blockIdx.x * PT;
    const float* src = g_out_h + tok0 * 32;
    for (int n = tid; n < PT * 32; n += 256) {
        int i = n >> 5, h = n & 31;
        float v = src[n];
        h_s[i * 72 + 2 * h]     = v;
        h_s[i * 72 + 2 * h + 1] = v;
    }
    __syncthreads();

    const int warp = tid >> 5, lane = tid & 31;
    const int p = ((warp & 3) << 5) + lane;        // 0..127
    const int tokbase = (warp >> 2) * 64;

    ull wreg[32];
#pragma unroll
    for (int h = 0; h < 32; ++h)
        wreg[h] = *(const ull*)&w_s[h * 260 + 2 * p];
    const ull b2 = *(const ull*)&b_s[2 * p];

#pragma unroll 1
    for (int tg = 0; tg < 16; ++tg) {
        const int tk = tokbase + tg * 4;
        ull a0 = b2, a1 = b2, a2 = b2, a3 = b2;
        const float* h0p = &h_s[(tk + 0) * 72];
        const float* h1p = &h_s[(tk + 1) * 72];
        const float* h2p = &h_s[(tk + 2) * 72];
        const float* h3p = &h_s[(tk + 3) * 72];
#pragma unroll
        for (int hq = 0; hq < 8; ++hq) {
            ulonglong2 qa0 = *(const ulonglong2*)(h0p + hq * 8);
            ulonglong2 qb0 = *(const ulonglong2*)(h0p + hq * 8 + 4);
            ulonglong2 qa1 = *(const ulonglong2*)(h1p + hq * 8);
            ulonglong2 qb1 = *(const ulonglong2*)(h1p + hq * 8 + 4);
            ulonglong2 qa2 = *(const ulonglong2*)(h2p + hq * 8);
            ulonglong2 qb2 = *(const ulonglong2*)(h2p + hq * 8 + 4);
            ulonglong2 qa3 = *(const ulonglong2*)(h3p + hq * 8);
            ulonglong2 qb3 = *(const ulonglong2*)(h3p + hq * 8 + 4);
            a0 = fma2(wreg[hq*4+0], qa0.x, a0);
            a1 = fma2(wreg[hq*4+0], qa1.x, a1);
            a2 = fma2(wreg[hq*4+0], qa2.x, a2);
            a3 = fma2(wreg[hq*4+0], qa3.x, a3);
            a0 = fma2(wreg[hq*4+1], qa0.y, a0);
            a1 = fma2(wreg[hq*4+1], qa1.y, a1);
            a2 = fma2(wreg[hq*4+1], qa2.y, a2);
            a3 = fma2(wreg[hq*4+1], qa3.y, a3);
            a0 = fma2(wreg[hq*4+2], qb0.x, a0);
            a1 = fma2(wreg[hq*4+2], qb1.x, a1);
            a2 = fma2(wreg[hq*4+2], qb2.x, a2);
            a3 = fma2(wreg[hq*4+2], qb3.x, a3);
            a0 = fma2(wreg[hq*4+3], qb0.y, a0);
            a1 = fma2(wreg[hq*4+3], qb1.y, a1);
            a2 = fma2(wreg[hq*4+3], qb2.y, a2);
            a3 = fma2(wreg[hq*4+3], qb3.y, a3);
        }
        float* outp = &pred[(tok0 + tk) * VOCABn + 2 * p];
        *(ull*)(outp + 0 * VOCABn) = a0;
        *(ull*)(outp + 1 * VOCABn) = a1;
        *(ull*)(outp + 2 * VOCABn) = a2;
        *(ull*)(outp + 3 * VOCABn) = a3;
    }

    // tail pair 128 (v = 256, 257)
    if (tid < PT) {
        ull acc = *(const ull*)&b_s[256];
        const float* hp = &h_s[tid * 72];
#pragma unroll
        for (int h = 0; h < 32; ++h)
            acc = fma2(*(const ull*)&w_s[h * 260 + 256],
                       *(const ull*)(hp + 2 * h), acc);
        *(ull*)&pred[(tok0 + tid) * VOCABn + 256] = acc;
    }
}

// ---------------------------------------------------------------------------

extern "C" void kernel_launch(void* const* d_in, const int* in_sizes, int n_in,
                              void* d_out, int out_size)
{
    const int*   x     = (const int*)  d_in[0];
    const float* emb   = (const float*)d_in[1];
    const float* wih0  = (const float*)d_in[2];
    const float* whh0  = (const float*)d_in[3];
    const float* bih0  = (const float*)d_in[4];
    const float* bhh0  = (const float*)d_in[5];
    const float* wih1  = (const float*)d_in[6];
    const float* whh1  = (const float*)d_in[7];
    const float* bih1  = (const float*)d_in[8];
    const float* bhh1  = (const float*)d_in[9];
    const float* wih2  = (const float*)d_in[10];
    const float* whh2  = (const float*)d_in[11];
    const float* bih2  = (const float*)d_in[12];
    const float* bhh2  = (const float*)d_in[13];
    const float* wh2e  = (const float*)d_in[14];
    const float* bh2e  = (const float*)d_in[15];
    const float* w_out = (const float*)d_in[16];
    const float* b_out = (const float*)d_in[17];
    float* pred = (float*)d_out;

    cudaFuncSetAttribute(rnn_kernel, cudaFuncAttributeMaxDynamicSharedMemorySize, SMEM_BYTES);
    cudaFuncSetAttribute(proj_kernel, cudaFuncAttributeMaxDynamicSharedMemorySize, PROJ_DYN_BYTES);

    prep_kernel<<<VOCABn, 96>>>(wih0, emb);
    rnn_kernel<<<Rn, 256, SMEM_BYTES>>>(x,
        wih0, whh0, bih0, bhh0,
        wih1, whh1, bih1, bhh1,
        wih2, whh2, bih2, bhh2,
        wh2e, bh2e);
    proj_kernel<<<NTOK / PT, 256, PROJ_DYN_BYTES>>>(w_out, b_out, pred);
}